// round 11
// baseline (speedup 1.0000x reference)
#include <cuda_runtime.h>
#include <cuda_fp16.h>
#include <math.h>
#include <stdint.h>

// Problem constants
#define B_   8
#define S_   1024
#define D_   1024
#define H_   8
#define HD_  128
#define PREFIX_LEN 77
#define MASKED_BIAS -10000.0f

// Scratch (no cudaMalloc allowed)
__device__ __half g_xh[B_ * S_ * D_];
__device__ __half g_wah[D_ * 3 * D_];
__device__ __half g_wph[D_ * D_];
__device__ __half g_qkv[B_ * S_ * 3 * D_];
__device__ __half g_attn[B_ * S_ * D_];

// ===========================================================================
// helpers
// ===========================================================================
__device__ __forceinline__ uint32_t s2u(const void* p) {
    return (uint32_t)__cvta_generic_to_shared((void*)p);
}
#define CP_ASYNC16(dst_u32, src_ptr) \
    asm volatile("cp.async.cg.shared.global [%0], [%1], 16;" \
                 :: "r"(dst_u32), "l"(src_ptr))
#define CP_COMMIT() asm volatile("cp.async.commit_group;" ::: "memory")
#define CP_WAIT0()  asm volatile("cp.async.wait_group 0;"  ::: "memory")
#define CP_WAIT1()  asm volatile("cp.async.wait_group 1;"  ::: "memory")

#define LDSM_X4(r0, r1, r2, r3, addr) \
    asm volatile("ldmatrix.sync.aligned.m8n8.x4.shared.b16 {%0,%1,%2,%3}, [%4];" \
        : "=r"(r0), "=r"(r1), "=r"(r2), "=r"(r3) : "r"(addr))
#define LDSM_X4_T(r0, r1, r2, r3, addr) \
    asm volatile("ldmatrix.sync.aligned.m8n8.x4.trans.shared.b16 {%0,%1,%2,%3}, [%4];" \
        : "=r"(r0), "=r"(r1), "=r"(r2), "=r"(r3) : "r"(addr))

#define MMA_F16(d, a0, a1, a2, a3, b0, b1) \
    asm volatile( \
        "mma.sync.aligned.m16n8k16.row.col.f32.f16.f16.f32 " \
        "{%0,%1,%2,%3}, {%4,%5,%6,%7}, {%8,%9}, {%0,%1,%2,%3};" \
        : "+f"((d)[0]), "+f"((d)[1]), "+f"((d)[2]), "+f"((d)[3]) \
        : "r"(a0), "r"(a1), "r"(a2), "r"(a3), "r"(b0), "r"(b1))

__device__ __forceinline__ uint32_t h2u(__half2 v) {
    return *(uint32_t*)&v;
}

// ===========================================================================
// fused fp32 -> fp16 conversion prepass
// ===========================================================================
#define N4_X  (B_ * S_ * D_ / 4)
#define N4_WA (3 * D_ * D_ / 4)
#define N4_WP (D_ * D_ / 4)
#define N4_TOTAL (N4_X + N4_WA + N4_WP)

__global__ __launch_bounds__(256) void f2h_all(
    const float* __restrict__ x, const float* __restrict__ wa,
    const float* __restrict__ wp,
    __half* __restrict__ xh, __half* __restrict__ wah, __half* __restrict__ wph)
{
    int i = blockIdx.x * blockDim.x + threadIdx.x;
    if (i >= N4_TOTAL) return;
    const float* src;
    __half* dst;
    int j;
    if (i < N4_X)              { src = x;  dst = xh;  j = i; }
    else if (i < N4_X + N4_WA) { src = wa; dst = wah; j = i - N4_X; }
    else                       { src = wp; dst = wph; j = i - N4_X - N4_WA; }
    float4 v = ((const float4*)src)[j];
    __half2* d2 = (__half2*)dst;
    d2[2 * j]     = __floats2half2_rn(v.x, v.y);
    d2[2 * j + 1] = __floats2half2_rn(v.z, v.w);
}

// ===========================================================================
// FP16 mma GEMM (unchanged)
// ===========================================================================
#define KKg 1024
#define BKg 64
#define NCHg (KKg / BKg)
#define SA_H 72
#define SB_H 136
#define A_BYTES (128 * SA_H * 2)
#define B_BYTES (BKg * SB_H * 2)
#define STAGE_BYTES (A_BYTES + B_BYTES)
#define GEMM_SMEM (3 * STAGE_BYTES)

template <bool OUT_HALF>
__global__ __launch_bounds__(256, 2) void gemm_mma_f16(
    const __half* __restrict__ A, const __half* __restrict__ Bw,
    const float* __restrict__ bias, void* __restrict__ Cv, int N)
{
    extern __shared__ char smraw[];
    const uint32_t su = s2u(smraw);

    const int t    = threadIdx.x;
    const int wid  = t >> 5;
    const int lane = t & 31;
    const int g    = lane >> 2;
    const int tq   = lane & 3;
    const int wm   = wid >> 2;
    const int wn   = wid & 3;
    const int m0   = blockIdx.y * 128;
    const int n0   = blockIdx.x * 128;

    const int l15  = lane & 15;
    const int l7   = lane & 7;
    const int hi8a = (lane & 16) ? 8 : 0;
    const int hi8b = (lane & 8)  ? 8 : 0;

    auto load_chunk = [&](int ch, int stg) {
        const int k0 = ch * BKg;
        const uint32_t base = su + (uint32_t)stg * STAGE_BYTES;
        #pragma unroll
        for (int i = 0; i < 4; i++) {
            int idx = t + i * 256;
            int r = idx >> 3, c = idx & 7;
            uint32_t dst = base + (uint32_t)(r * (SA_H * 2) + c * 16);
            const __half* src = A + (long)(m0 + r) * KKg + k0 + c * 8;
            CP_ASYNC16(dst, src);
        }
        #pragma unroll
        for (int i = 0; i < 4; i++) {
            int idx = t + i * 256;
            int r = idx >> 4, c = idx & 15;
            uint32_t dst = base + A_BYTES + (uint32_t)(r * (SB_H * 2) + c * 16);
            const __half* src = Bw + (long)(k0 + r) * N + n0 + c * 8;
            CP_ASYNC16(dst, src);
        }
    };

    load_chunk(0, 0); CP_COMMIT();
    load_chunk(1, 1); CP_COMMIT();

    float acc[4][4][4];
    #pragma unroll
    for (int mt = 0; mt < 4; mt++)
        #pragma unroll
        for (int nt = 0; nt < 4; nt++)
            #pragma unroll
            for (int r = 0; r < 4; r++) acc[mt][nt][r] = 0.0f;

    int stage = 0;
    for (int i = 0; i < NCHg; i++) {
        if (i + 2 < NCHg) CP_WAIT1(); else CP_WAIT0();
        __syncthreads();

        if (i + 2 < NCHg) {
            int nstg = stage + 2; if (nstg >= 3) nstg -= 3;
            load_chunk(i + 2, nstg);
        }
        CP_COMMIT();

        const uint32_t sa = su + (uint32_t)stage * STAGE_BYTES;
        const uint32_t sb = sa + A_BYTES;

        #pragma unroll
        for (int ks = 0; ks < 4; ks++) {
            uint32_t af[4][4], bf[4][2];
            #pragma unroll
            for (int mt = 0; mt < 4; mt++) {
                uint32_t addr = sa + 2u * (uint32_t)(
                    (wm * 64 + mt * 16 + l15) * SA_H + ks * 16 + hi8a);
                LDSM_X4(af[mt][0], af[mt][1], af[mt][2], af[mt][3], addr);
            }
            #pragma unroll
            for (int np = 0; np < 2; np++) {
                uint32_t addr = sb + 2u * (uint32_t)(
                    (ks * 16 + l7 + hi8b) * SB_H + wn * 32 + np * 16 + hi8a);
                LDSM_X4_T(bf[2 * np][0], bf[2 * np][1],
                          bf[2 * np + 1][0], bf[2 * np + 1][1], addr);
            }
            #pragma unroll
            for (int mt = 0; mt < 4; mt++)
                #pragma unroll
                for (int nt = 0; nt < 4; nt++)
                    MMA_F16(acc[mt][nt], af[mt][0], af[mt][1], af[mt][2],
                            af[mt][3], bf[nt][0], bf[nt][1]);
        }
        if (++stage == 3) stage = 0;
    }

    #pragma unroll
    for (int nt = 0; nt < 4; nt++) {
        const int col = n0 + wn * 32 + nt * 8 + tq * 2;
        const float bx = bias[col];
        const float by = bias[col + 1];
        #pragma unroll
        for (int mt = 0; mt < 4; mt++) {
            const int row = m0 + wm * 64 + mt * 16 + g;
            if (OUT_HALF) {
                __half* C = (__half*)Cv;
                *(__half2*)&C[(long)row * N + col] =
                    __floats2half2_rn(acc[mt][nt][0] + bx, acc[mt][nt][1] + by);
                *(__half2*)&C[(long)(row + 8) * N + col] =
                    __floats2half2_rn(acc[mt][nt][2] + bx, acc[mt][nt][3] + by);
            } else {
                float* C = (float*)Cv;
                *(float2*)&C[(long)row * N + col] =
                    make_float2(acc[mt][nt][0] + bx, acc[mt][nt][1] + by);
                *(float2*)&C[(long)(row + 8) * N + col] =
                    make_float2(acc[mt][nt][2] + bx, acc[mt][nt][3] + by);
            }
        }
    }
}

// ===========================================================================
// FP16 flash attention: 64-query CTAs, 128 threads, 3 CTAs/SM.
// 4 buffers of 64x136 halves: [Q -> V-odd][K-even][K-odd][V-even].
// ===========================================================================
#define AST 136
#define QROWS 64
#define BUFH (QROWS * AST)                 // 8704 halves per buffer
#define ATTN_SMEM (4 * BUFH * 2)           // 69632 bytes

__global__ __launch_bounds__(128, 3) void attn_mma_f16(
    const __half* __restrict__ qkv,     // [B,S,3D] fp16
    const float* __restrict__ amask,    // [B,1,1,S] fp32
    __half* __restrict__ aout)          // [B,S,D] fp16
{
    extern __shared__ __half smh[];
    const uint32_t su = s2u(smh);

    const int t    = threadIdx.x;      // 0..127
    const int wid  = t >> 5;           // 0..3
    const int lane = t & 31;
    const int g    = lane >> 2;
    const int tq   = lane & 3;
    const int qt   = gridDim.x - 1 - blockIdx.x;   // largest-work first
    const int q0   = qt * QROWS;
    const int bh   = blockIdx.y;
    const int b    = bh >> 3;
    const int h    = bh & 7;
    const int rb   = wid * 16;

    const int l15  = lane & 15;
    const int l7   = lane & 7;
    const int hi8a = (lane & 16) ? 8 : 0;
    const int hi8b = (lane & 8)  ? 8 : 0;

    const float qscale = rsqrtf((float)HD_);
    int nkt = qt + 1;
    if (nkt < 2) nkt = 2;

    // Buffer bases (byte addresses): A=Q/V-odd, B=K-even, C=K-odd, D=V-even
    const uint32_t bufA = su;
    const uint32_t bufB = su + 2u * (uint32_t)BUFH;
    const uint32_t bufC = su + 4u * (uint32_t)BUFH;
    const uint32_t bufD = su + 6u * (uint32_t)BUFH;

    // ---- issue Q tile load into buffer A ----
    #pragma unroll
    for (int i = 0; i < 8; i++) {
        int idx = t + i * 128;
        int row = idx >> 4;
        int c   = idx & 15;
        uint32_t dst = bufA + 2u * (uint32_t)(row * AST + c * 8);
        CP_ASYNC16(dst, &qkv[(long)(b * S_ + q0 + row) * (3 * D_) + h * HD_ + c * 8]);
    }
    CP_COMMIT();

    auto load_kv = [&](int kt) {
        const uint32_t kbase = (kt & 1) ? bufC : bufB;
        const uint32_t vbase = (kt & 1) ? bufA : bufD;
        #pragma unroll
        for (int i = 0; i < 16; i++) {
            int idx = t + i * 128;          // 0..2047; first 1024 K, rest V
            int row = (idx & 1023) >> 4;
            int c   = idx & 15;
            long src = (long)(b * S_ + kt * 64 + row) * (3 * D_) + h * HD_ + c * 8;
            if (idx < 1024) {
                CP_ASYNC16(kbase + 2u * (uint32_t)(row * AST + c * 8),
                           &qkv[src + D_]);
            } else {
                CP_ASYNC16(vbase + 2u * (uint32_t)(row * AST + c * 8),
                           &qkv[src + 2 * D_]);
            }
        }
        CP_COMMIT();
    };

    load_kv(0);   // K0 -> B, V0 -> D

    CP_WAIT1();               // Q resident (KV0 in flight)
    __syncthreads();
    uint32_t qf[8][4];
    #pragma unroll
    for (int ks = 0; ks < 8; ks++) {
        LDSM_X4(qf[ks][0], qf[ks][1], qf[ks][2], qf[ks][3],
                bufA + 2u * (uint32_t)((rb + l15) * AST + ks * 16 + hi8a));
    }
    __syncthreads();          // all warps done reading Q before V(1) -> bufA

    float o[16][4];
    #pragma unroll
    for (int nt = 0; nt < 16; nt++)
        #pragma unroll
        for (int r = 0; r < 4; r++) o[nt][r] = 0.0f;
    float m0 = -1e30f, m1 = -1e30f, l0 = 0.0f, l1 = 0.0f;

    const int row0 = q0 + rb + g;
    const int row1 = row0 + 8;

    for (int kt = 0; kt < nkt; kt++) {
        if (kt + 1 < nkt) { load_kv(kt + 1); CP_WAIT1(); }
        else              { CP_WAIT0(); }
        __syncthreads();

        const uint32_t Ku = (kt & 1) ? bufC : bufB;
        const uint32_t Vu = (kt & 1) ? bufA : bufD;

        // ---- S = Q @ K^T : warp tile 16x64 ----
        float sacc[8][4];
        #pragma unroll
        for (int nt = 0; nt < 8; nt++)
            #pragma unroll
            for (int r = 0; r < 4; r++) sacc[nt][r] = 0.0f;

        #pragma unroll
        for (int ks = 0; ks < 8; ks++) {
            #pragma unroll
            for (int np = 0; np < 4; np++) {
                uint32_t b0, b1, b2, b3;
                LDSM_X4(b0, b1, b2, b3,
                        Ku + 2u * (uint32_t)((np * 16 + l7 + hi8a) * AST + ks * 16 + hi8b));
                MMA_F16(sacc[2 * np],     qf[ks][0], qf[ks][1], qf[ks][2], qf[ks][3], b0, b1);
                MMA_F16(sacc[2 * np + 1], qf[ks][0], qf[ks][1], qf[ks][2], qf[ks][3], b2, b3);
            }
        }

        // ---- scale + mask + online softmax ----
        float mloc0 = -1e30f, mloc1 = -1e30f;
        #pragma unroll
        for (int nt = 0; nt < 8; nt++) {
            const int c0 = kt * 64 + nt * 8 + 2 * tq;
            const int c1 = c0 + 1;
            const float am0 = amask[b * S_ + c0];
            const float am1 = amask[b * S_ + c1];
            bool ok00 = (row0 < PREFIX_LEN) ? (c0 < PREFIX_LEN) : (c0 <= row0);
            bool ok01 = (row0 < PREFIX_LEN) ? (c1 < PREFIX_LEN) : (c1 <= row0);
            bool ok10 = (row1 < PREFIX_LEN) ? (c0 < PREFIX_LEN) : (c0 <= row1);
            bool ok11 = (row1 < PREFIX_LEN) ? (c1 < PREFIX_LEN) : (c1 <= row1);
            sacc[nt][0] = (ok00 ? sacc[nt][0] * qscale : MASKED_BIAS) + am0;
            sacc[nt][1] = (ok01 ? sacc[nt][1] * qscale : MASKED_BIAS) + am1;
            sacc[nt][2] = (ok10 ? sacc[nt][2] * qscale : MASKED_BIAS) + am0;
            sacc[nt][3] = (ok11 ? sacc[nt][3] * qscale : MASKED_BIAS) + am1;
            mloc0 = fmaxf(mloc0, fmaxf(sacc[nt][0], sacc[nt][1]));
            mloc1 = fmaxf(mloc1, fmaxf(sacc[nt][2], sacc[nt][3]));
        }
        mloc0 = fmaxf(mloc0, __shfl_xor_sync(0xFFFFFFFF, mloc0, 1));
        mloc0 = fmaxf(mloc0, __shfl_xor_sync(0xFFFFFFFF, mloc0, 2));
        mloc1 = fmaxf(mloc1, __shfl_xor_sync(0xFFFFFFFF, mloc1, 1));
        mloc1 = fmaxf(mloc1, __shfl_xor_sync(0xFFFFFFFF, mloc1, 2));

        const float mn0 = fmaxf(m0, mloc0);
        const float mn1 = fmaxf(m1, mloc1);
        const float sc0 = __expf(m0 - mn0);
        const float sc1 = __expf(m1 - mn1);
        m0 = mn0; m1 = mn1;

        float ls0 = 0.0f, ls1 = 0.0f;
        #pragma unroll
        for (int nt = 0; nt < 8; nt++) {
            sacc[nt][0] = __expf(sacc[nt][0] - mn0);
            sacc[nt][1] = __expf(sacc[nt][1] - mn0);
            sacc[nt][2] = __expf(sacc[nt][2] - mn1);
            sacc[nt][3] = __expf(sacc[nt][3] - mn1);
            ls0 += sacc[nt][0] + sacc[nt][1];
            ls1 += sacc[nt][2] + sacc[nt][3];
        }
        ls0 += __shfl_xor_sync(0xFFFFFFFF, ls0, 1);
        ls0 += __shfl_xor_sync(0xFFFFFFFF, ls0, 2);
        ls1 += __shfl_xor_sync(0xFFFFFFFF, ls1, 1);
        ls1 += __shfl_xor_sync(0xFFFFFFFF, ls1, 2);
        l0 = l0 * sc0 + ls0;
        l1 = l1 * sc1 + ls1;

        #pragma unroll
        for (int nt = 0; nt < 16; nt++) {
            o[nt][0] *= sc0; o[nt][1] *= sc0;
            o[nt][2] *= sc1; o[nt][3] *= sc1;
        }

        // ---- O += P @ V : P stays in registers ----
        #pragma unroll
        for (int kk = 0; kk < 4; kk++) {
            uint32_t pa0 = h2u(__floats2half2_rn(sacc[2 * kk][0],     sacc[2 * kk][1]));
            uint32_t pa1 = h2u(__floats2half2_rn(sacc[2 * kk][2],     sacc[2 * kk][3]));
            uint32_t pa2 = h2u(__floats2half2_rn(sacc[2 * kk + 1][0], sacc[2 * kk + 1][1]));
            uint32_t pa3 = h2u(__floats2half2_rn(sacc[2 * kk + 1][2], sacc[2 * kk + 1][3]));
            #pragma unroll
            for (int np = 0; np < 8; np++) {
                uint32_t b0, b1, b2, b3;
                LDSM_X4_T(b0, b1, b2, b3,
                          Vu + 2u * (uint32_t)((kk * 16 + l7 + hi8b) * AST + np * 16 + hi8a));
                MMA_F16(o[2 * np],     pa0, pa1, pa2, pa3, b0, b1);
                MMA_F16(o[2 * np + 1], pa0, pa1, pa2, pa3, b2, b3);
            }
        }

        __syncthreads();
    }

    // ---- epilogue ----
    const float inv0 = 1.0f / l0;
    const float inv1 = 1.0f / l1;
    #pragma unroll
    for (int nt = 0; nt < 16; nt++) {
        const int col = h * HD_ + nt * 8 + 2 * tq;
        *(__half2*)&aout[(long)(b * S_ + row0) * D_ + col] =
            __floats2half2_rn(o[nt][0] * inv0, o[nt][1] * inv0);
        *(__half2*)&aout[(long)(b * S_ + row1) * D_ + col] =
            __floats2half2_rn(o[nt][2] * inv1, o[nt][3] * inv1);
    }
}

// ===========================================================================
extern "C" void kernel_launch(void* const* d_in, const int* in_sizes, int n_in,
                              void* d_out, int out_size)
{
    const float* x      = (const float*)d_in[0];
    const float* amask  = (const float*)d_in[1];
    const float* W_attn = (const float*)d_in[2];
    const float* b_attn = (const float*)d_in[3];
    const float* W_proj = (const float*)d_in[4];
    const float* b_proj = (const float*)d_in[5];
    float* out = (float*)d_out;

    __half *xh, *wah, *wph, *qkv, *attn;
    cudaGetSymbolAddress((void**)&xh,   g_xh);
    cudaGetSymbolAddress((void**)&wah,  g_wah);
    cudaGetSymbolAddress((void**)&wph,  g_wph);
    cudaGetSymbolAddress((void**)&qkv,  g_qkv);
    cudaGetSymbolAddress((void**)&attn, g_attn);

    cudaFuncSetAttribute(gemm_mma_f16<true>,
                         cudaFuncAttributeMaxDynamicSharedMemorySize, GEMM_SMEM);
    cudaFuncSetAttribute(gemm_mma_f16<false>,
                         cudaFuncAttributeMaxDynamicSharedMemorySize, GEMM_SMEM);
    cudaFuncSetAttribute(attn_mma_f16,
                         cudaFuncAttributeMaxDynamicSharedMemorySize, ATTN_SMEM);

    const int M = B_ * S_;   // 8192

    // 0) fused fp32 -> fp16 prepass
    f2h_all<<<(N4_TOTAL + 255) / 256, 256>>>(x, W_attn, W_proj, xh, wah, wph);

    // 1) QKV GEMM (fp16 mma) -> fp16
    {
        dim3 grid((3 * D_) / 128, M / 128);
        gemm_mma_f16<true><<<grid, 256, GEMM_SMEM>>>(xh, wah, b_attn, qkv, 3 * D_);
    }

    // 2) Tensor-core flash attention (fp16, 64-query CTAs, 3 CTAs/SM)
    {
        dim3 grid(S_ / QROWS, B_ * H_);
        attn_mma_f16<<<grid, 128, ATTN_SMEM>>>(qkv, amask, attn);
    }

    // 3) Output projection (fp16 mma) -> fp32
    {
        dim3 grid(D_ / 128, M / 128);
        gemm_mma_f16<false><<<grid, 256, GEMM_SMEM>>>(attn, wph, b_proj, out, D_);
    }
}

// round 12
// speedup vs baseline: 1.0619x; 1.0619x over previous
#include <cuda_runtime.h>
#include <cuda_fp16.h>
#include <math.h>
#include <stdint.h>

// Problem constants
#define B_   8
#define S_   1024
#define D_   1024
#define H_   8
#define HD_  128
#define PREFIX_LEN 77
#define MASKED_BIAS -10000.0f

// Scratch (no cudaMalloc allowed)
__device__ __half g_xh[B_ * S_ * D_];
__device__ __half g_wah[D_ * 3 * D_];
__device__ __half g_wph[D_ * D_];
__device__ __half g_qkv[B_ * S_ * 3 * D_];
__device__ __half g_attn[B_ * S_ * D_];

// ===========================================================================
// helpers
// ===========================================================================
__device__ __forceinline__ uint32_t s2u(const void* p) {
    return (uint32_t)__cvta_generic_to_shared((void*)p);
}
#define CP_ASYNC16(dst_u32, src_ptr) \
    asm volatile("cp.async.cg.shared.global [%0], [%1], 16;" \
                 :: "r"(dst_u32), "l"(src_ptr))
#define CP_COMMIT() asm volatile("cp.async.commit_group;" ::: "memory")
#define CP_WAIT0()  asm volatile("cp.async.wait_group 0;"  ::: "memory")
#define CP_WAIT1()  asm volatile("cp.async.wait_group 1;"  ::: "memory")

#define LDSM_X4(r0, r1, r2, r3, addr) \
    asm volatile("ldmatrix.sync.aligned.m8n8.x4.shared.b16 {%0,%1,%2,%3}, [%4];" \
        : "=r"(r0), "=r"(r1), "=r"(r2), "=r"(r3) : "r"(addr))
#define LDSM_X4_T(r0, r1, r2, r3, addr) \
    asm volatile("ldmatrix.sync.aligned.m8n8.x4.trans.shared.b16 {%0,%1,%2,%3}, [%4];" \
        : "=r"(r0), "=r"(r1), "=r"(r2), "=r"(r3) : "r"(addr))

#define MMA_F16(d, a0, a1, a2, a3, b0, b1) \
    asm volatile( \
        "mma.sync.aligned.m16n8k16.row.col.f32.f16.f16.f32 " \
        "{%0,%1,%2,%3}, {%4,%5,%6,%7}, {%8,%9}, {%0,%1,%2,%3};" \
        : "+f"((d)[0]), "+f"((d)[1]), "+f"((d)[2]), "+f"((d)[3]) \
        : "r"(a0), "r"(a1), "r"(a2), "r"(a3), "r"(b0), "r"(b1))

__device__ __forceinline__ uint32_t h2u(__half2 v) {
    return *(uint32_t*)&v;
}

// ===========================================================================
// fused fp32 -> fp16 conversion prepass
// ===========================================================================
#define N4_X  (B_ * S_ * D_ / 4)
#define N4_WA (3 * D_ * D_ / 4)
#define N4_WP (D_ * D_ / 4)
#define N4_TOTAL (N4_X + N4_WA + N4_WP)

__global__ __launch_bounds__(256) void f2h_all(
    const float* __restrict__ x, const float* __restrict__ wa,
    const float* __restrict__ wp,
    __half* __restrict__ xh, __half* __restrict__ wah, __half* __restrict__ wph)
{
    int i = blockIdx.x * blockDim.x + threadIdx.x;
    if (i >= N4_TOTAL) return;
    const float* src;
    __half* dst;
    int j;
    if (i < N4_X)              { src = x;  dst = xh;  j = i; }
    else if (i < N4_X + N4_WA) { src = wa; dst = wah; j = i - N4_X; }
    else                       { src = wp; dst = wph; j = i - N4_X - N4_WA; }
    float4 v = ((const float4*)src)[j];
    __half2* d2 = (__half2*)dst;
    d2[2 * j]     = __floats2half2_rn(v.x, v.y);
    d2[2 * j + 1] = __floats2half2_rn(v.z, v.w);
}

// ===========================================================================
// FP16 mma GEMM (unchanged — proven)
// ===========================================================================
#define KKg 1024
#define BKg 64
#define NCHg (KKg / BKg)
#define SA_H 72
#define SB_H 136
#define A_BYTES (128 * SA_H * 2)
#define B_BYTES (BKg * SB_H * 2)
#define STAGE_BYTES (A_BYTES + B_BYTES)
#define GEMM_SMEM (3 * STAGE_BYTES)

template <bool OUT_HALF>
__global__ __launch_bounds__(256, 2) void gemm_mma_f16(
    const __half* __restrict__ A, const __half* __restrict__ Bw,
    const float* __restrict__ bias, void* __restrict__ Cv, int N)
{
    extern __shared__ char smraw[];
    const uint32_t su = s2u(smraw);

    const int t    = threadIdx.x;
    const int wid  = t >> 5;
    const int lane = t & 31;
    const int g    = lane >> 2;
    const int tq   = lane & 3;
    const int wm   = wid >> 2;
    const int wn   = wid & 3;
    const int m0   = blockIdx.y * 128;
    const int n0   = blockIdx.x * 128;

    const int l15  = lane & 15;
    const int l7   = lane & 7;
    const int hi8a = (lane & 16) ? 8 : 0;
    const int hi8b = (lane & 8)  ? 8 : 0;

    auto load_chunk = [&](int ch, int stg) {
        const int k0 = ch * BKg;
        const uint32_t base = su + (uint32_t)stg * STAGE_BYTES;
        #pragma unroll
        for (int i = 0; i < 4; i++) {
            int idx = t + i * 256;
            int r = idx >> 3, c = idx & 7;
            uint32_t dst = base + (uint32_t)(r * (SA_H * 2) + c * 16);
            const __half* src = A + (long)(m0 + r) * KKg + k0 + c * 8;
            CP_ASYNC16(dst, src);
        }
        #pragma unroll
        for (int i = 0; i < 4; i++) {
            int idx = t + i * 256;
            int r = idx >> 4, c = idx & 15;
            uint32_t dst = base + A_BYTES + (uint32_t)(r * (SB_H * 2) + c * 16);
            const __half* src = Bw + (long)(k0 + r) * N + n0 + c * 8;
            CP_ASYNC16(dst, src);
        }
    };

    load_chunk(0, 0); CP_COMMIT();
    load_chunk(1, 1); CP_COMMIT();

    float acc[4][4][4];
    #pragma unroll
    for (int mt = 0; mt < 4; mt++)
        #pragma unroll
        for (int nt = 0; nt < 4; nt++)
            #pragma unroll
            for (int r = 0; r < 4; r++) acc[mt][nt][r] = 0.0f;

    int stage = 0;
    for (int i = 0; i < NCHg; i++) {
        if (i + 2 < NCHg) CP_WAIT1(); else CP_WAIT0();
        __syncthreads();

        if (i + 2 < NCHg) {
            int nstg = stage + 2; if (nstg >= 3) nstg -= 3;
            load_chunk(i + 2, nstg);
        }
        CP_COMMIT();

        const uint32_t sa = su + (uint32_t)stage * STAGE_BYTES;
        const uint32_t sb = sa + A_BYTES;

        #pragma unroll
        for (int ks = 0; ks < 4; ks++) {
            uint32_t af[4][4], bf[4][2];
            #pragma unroll
            for (int mt = 0; mt < 4; mt++) {
                uint32_t addr = sa + 2u * (uint32_t)(
                    (wm * 64 + mt * 16 + l15) * SA_H + ks * 16 + hi8a);
                LDSM_X4(af[mt][0], af[mt][1], af[mt][2], af[mt][3], addr);
            }
            #pragma unroll
            for (int np = 0; np < 2; np++) {
                uint32_t addr = sb + 2u * (uint32_t)(
                    (ks * 16 + l7 + hi8b) * SB_H + wn * 32 + np * 16 + hi8a);
                LDSM_X4_T(bf[2 * np][0], bf[2 * np][1],
                          bf[2 * np + 1][0], bf[2 * np + 1][1], addr);
            }
            #pragma unroll
            for (int mt = 0; mt < 4; mt++)
                #pragma unroll
                for (int nt = 0; nt < 4; nt++)
                    MMA_F16(acc[mt][nt], af[mt][0], af[mt][1], af[mt][2],
                            af[mt][3], bf[nt][0], bf[nt][1]);
        }
        if (++stage == 3) stage = 0;
    }

    #pragma unroll
    for (int nt = 0; nt < 4; nt++) {
        const int col = n0 + wn * 32 + nt * 8 + tq * 2;
        const float bx = bias[col];
        const float by = bias[col + 1];
        #pragma unroll
        for (int mt = 0; mt < 4; mt++) {
            const int row = m0 + wm * 64 + mt * 16 + g;
            if (OUT_HALF) {
                __half* C = (__half*)Cv;
                *(__half2*)&C[(long)row * N + col] =
                    __floats2half2_rn(acc[mt][nt][0] + bx, acc[mt][nt][1] + by);
                *(__half2*)&C[(long)(row + 8) * N + col] =
                    __floats2half2_rn(acc[mt][nt][2] + bx, acc[mt][nt][3] + by);
            } else {
                float* C = (float*)Cv;
                *(float2*)&C[(long)row * N + col] =
                    make_float2(acc[mt][nt][0] + bx, acc[mt][nt][1] + by);
                *(float2*)&C[(long)(row + 8) * N + col] =
                    make_float2(acc[mt][nt][2] + bx, acc[mt][nt][3] + by);
            }
        }
    }
}

// ===========================================================================
// FP16 flash attention: 64-query CTAs, 128 threads, 2 CTAs/SM (round-10
// winner) + interior-tile fast path (kt < qt tiles are provably unmasked).
// ===========================================================================
#define AST 136
#define QROWS 64
#define KV_STAGE (64 * AST * 2)            // K+V per stage (halves)
#define KV_OFF (QROWS * AST)               // 8704 halves
#define ATTN_SMEM ((KV_OFF + 2 * KV_STAGE) * 2)   // 87040 bytes

__global__ __launch_bounds__(128, 2) void attn_mma_f16(
    const __half* __restrict__ qkv,     // [B,S,3D] fp16
    const float* __restrict__ amask,    // [B,1,1,S] fp32
    __half* __restrict__ aout)          // [B,S,D] fp16
{
    extern __shared__ __half smh[];
    const uint32_t su = s2u(smh);
    const uint32_t Qu = su;

    const int t    = threadIdx.x;      // 0..127
    const int wid  = t >> 5;           // 0..3
    const int lane = t & 31;
    const int g    = lane >> 2;
    const int tq   = lane & 3;
    const int qt   = gridDim.x - 1 - blockIdx.x;   // largest-work first
    const int q0   = qt * QROWS;
    const int bh   = blockIdx.y;
    const int b    = bh >> 3;
    const int h    = bh & 7;
    const int rb   = wid * 16;

    const int l15  = lane & 15;
    const int l7   = lane & 7;
    const int hi8a = (lane & 16) ? 8 : 0;
    const int hi8b = (lane & 8)  ? 8 : 0;

    const float qscale = rsqrtf((float)HD_);
    int nkt = qt + 1;
    if (nkt < 2) nkt = 2;

    // ---- issue Q tile load ----
    #pragma unroll
    for (int i = 0; i < 8; i++) {
        int idx = t + i * 128;
        int row = idx >> 4;
        int c   = idx & 15;
        uint32_t dst = su + 2u * (uint32_t)(row * AST + c * 8);
        CP_ASYNC16(dst, &qkv[(long)(b * S_ + q0 + row) * (3 * D_) + h * HD_ + c * 8]);
    }
    CP_COMMIT();

    auto load_kv = [&](int kt, int stg) {
        const uint32_t kbase = su + 2u * (uint32_t)(KV_OFF + stg * KV_STAGE);
        #pragma unroll
        for (int i = 0; i < 16; i++) {
            int idx = t + i * 128;          // 0..2047; first 1024 K, rest V
            int row = (idx & 1023) >> 4;
            int c   = idx & 15;
            long src = (long)(b * S_ + kt * 64 + row) * (3 * D_) + h * HD_ + c * 8;
            if (idx < 1024) {
                CP_ASYNC16(kbase + 2u * (uint32_t)(row * AST + c * 8),
                           &qkv[src + D_]);
            } else {
                CP_ASYNC16(kbase + 2u * (uint32_t)((64 + row) * AST + c * 8),
                           &qkv[src + 2 * D_]);
            }
        }
        CP_COMMIT();
    };

    load_kv(0, 0);

    CP_WAIT1();               // Q resident (KV0 in flight)
    __syncthreads();
    uint32_t qf[8][4];
    #pragma unroll
    for (int ks = 0; ks < 8; ks++) {
        LDSM_X4(qf[ks][0], qf[ks][1], qf[ks][2], qf[ks][3],
                Qu + 2u * (uint32_t)((rb + l15) * AST + ks * 16 + hi8a));
    }

    float o[16][4];
    #pragma unroll
    for (int nt = 0; nt < 16; nt++)
        #pragma unroll
        for (int r = 0; r < 4; r++) o[nt][r] = 0.0f;
    float m0 = -1e30f, m1 = -1e30f, l0 = 0.0f, l1 = 0.0f;

    const int row0 = q0 + rb + g;
    const int row1 = row0 + 8;

    for (int kt = 0; kt < nkt; kt++) {
        if (kt + 1 < nkt) { load_kv(kt + 1, (kt + 1) & 1); CP_WAIT1(); }
        else              { CP_WAIT0(); }
        __syncthreads();

        const uint32_t Ku = su + 2u * (uint32_t)(KV_OFF + (kt & 1) * KV_STAGE);
        const uint32_t Vu = Ku + 2u * (uint32_t)(64 * AST);

        // ---- S = Q @ K^T : warp tile 16x64 ----
        float sacc[8][4];
        #pragma unroll
        for (int nt = 0; nt < 8; nt++)
            #pragma unroll
            for (int r = 0; r < 4; r++) sacc[nt][r] = 0.0f;

        #pragma unroll
        for (int ks = 0; ks < 8; ks++) {
            #pragma unroll
            for (int np = 0; np < 4; np++) {
                uint32_t b0, b1, b2, b3;
                LDSM_X4(b0, b1, b2, b3,
                        Ku + 2u * (uint32_t)((np * 16 + l7 + hi8a) * AST + ks * 16 + hi8b));
                MMA_F16(sacc[2 * np],     qf[ks][0], qf[ks][1], qf[ks][2], qf[ks][3], b0, b1);
                MMA_F16(sacc[2 * np + 1], qf[ks][0], qf[ks][1], qf[ks][2], qf[ks][3], b2, b3);
            }
        }

        // ---- scale + mask + online softmax ----
        float mloc0 = -1e30f, mloc1 = -1e30f;
        if (kt < qt) {
            // Interior tile: provably fully unmasked (causal rows dominate
            // all cols < qt*64; prefix rows only in qt<=1 where cols<64<77).
            #pragma unroll
            for (int nt = 0; nt < 8; nt++) {
                const int c0 = kt * 64 + nt * 8 + 2 * tq;
                const float am0 = amask[b * S_ + c0];
                const float am1 = amask[b * S_ + c0 + 1];
                sacc[nt][0] = sacc[nt][0] * qscale + am0;
                sacc[nt][1] = sacc[nt][1] * qscale + am1;
                sacc[nt][2] = sacc[nt][2] * qscale + am0;
                sacc[nt][3] = sacc[nt][3] * qscale + am1;
                mloc0 = fmaxf(mloc0, fmaxf(sacc[nt][0], sacc[nt][1]));
                mloc1 = fmaxf(mloc1, fmaxf(sacc[nt][2], sacc[nt][3]));
            }
        } else {
            #pragma unroll
            for (int nt = 0; nt < 8; nt++) {
                const int c0 = kt * 64 + nt * 8 + 2 * tq;
                const int c1 = c0 + 1;
                const float am0 = amask[b * S_ + c0];
                const float am1 = amask[b * S_ + c1];
                bool ok00 = (row0 < PREFIX_LEN) ? (c0 < PREFIX_LEN) : (c0 <= row0);
                bool ok01 = (row0 < PREFIX_LEN) ? (c1 < PREFIX_LEN) : (c1 <= row0);
                bool ok10 = (row1 < PREFIX_LEN) ? (c0 < PREFIX_LEN) : (c0 <= row1);
                bool ok11 = (row1 < PREFIX_LEN) ? (c1 < PREFIX_LEN) : (c1 <= row1);
                sacc[nt][0] = (ok00 ? sacc[nt][0] * qscale : MASKED_BIAS) + am0;
                sacc[nt][1] = (ok01 ? sacc[nt][1] * qscale : MASKED_BIAS) + am1;
                sacc[nt][2] = (ok10 ? sacc[nt][2] * qscale : MASKED_BIAS) + am0;
                sacc[nt][3] = (ok11 ? sacc[nt][3] * qscale : MASKED_BIAS) + am1;
                mloc0 = fmaxf(mloc0, fmaxf(sacc[nt][0], sacc[nt][1]));
                mloc1 = fmaxf(mloc1, fmaxf(sacc[nt][2], sacc[nt][3]));
            }
        }
        mloc0 = fmaxf(mloc0, __shfl_xor_sync(0xFFFFFFFF, mloc0, 1));
        mloc0 = fmaxf(mloc0, __shfl_xor_sync(0xFFFFFFFF, mloc0, 2));
        mloc1 = fmaxf(mloc1, __shfl_xor_sync(0xFFFFFFFF, mloc1, 1));
        mloc1 = fmaxf(mloc1, __shfl_xor_sync(0xFFFFFFFF, mloc1, 2));

        const float mn0 = fmaxf(m0, mloc0);
        const float mn1 = fmaxf(m1, mloc1);
        const float sc0 = __expf(m0 - mn0);
        const float sc1 = __expf(m1 - mn1);
        m0 = mn0; m1 = mn1;

        float ls0 = 0.0f, ls1 = 0.0f;
        #pragma unroll
        for (int nt = 0; nt < 8; nt++) {
            sacc[nt][0] = __expf(sacc[nt][0] - mn0);
            sacc[nt][1] = __expf(sacc[nt][1] - mn0);
            sacc[nt][2] = __expf(sacc[nt][2] - mn1);
            sacc[nt][3] = __expf(sacc[nt][3] - mn1);
            ls0 += sacc[nt][0] + sacc[nt][1];
            ls1 += sacc[nt][2] + sacc[nt][3];
        }
        ls0 += __shfl_xor_sync(0xFFFFFFFF, ls0, 1);
        ls0 += __shfl_xor_sync(0xFFFFFFFF, ls0, 2);
        ls1 += __shfl_xor_sync(0xFFFFFFFF, ls1, 1);
        ls1 += __shfl_xor_sync(0xFFFFFFFF, ls1, 2);
        l0 = l0 * sc0 + ls0;
        l1 = l1 * sc1 + ls1;

        #pragma unroll
        for (int nt = 0; nt < 16; nt++) {
            o[nt][0] *= sc0; o[nt][1] *= sc0;
            o[nt][2] *= sc1; o[nt][3] *= sc1;
        }

        // ---- O += P @ V : P stays in registers ----
        #pragma unroll
        for (int kk = 0; kk < 4; kk++) {
            uint32_t pa0 = h2u(__floats2half2_rn(sacc[2 * kk][0],     sacc[2 * kk][1]));
            uint32_t pa1 = h2u(__floats2half2_rn(sacc[2 * kk][2],     sacc[2 * kk][3]));
            uint32_t pa2 = h2u(__floats2half2_rn(sacc[2 * kk + 1][0], sacc[2 * kk + 1][1]));
            uint32_t pa3 = h2u(__floats2half2_rn(sacc[2 * kk + 1][2], sacc[2 * kk + 1][3]));
            #pragma unroll
            for (int np = 0; np < 8; np++) {
                uint32_t b0, b1, b2, b3;
                LDSM_X4_T(b0, b1, b2, b3,
                          Vu + 2u * (uint32_t)((kk * 16 + l7 + hi8b) * AST + np * 16 + hi8a));
                MMA_F16(o[2 * np],     pa0, pa1, pa2, pa3, b0, b1);
                MMA_F16(o[2 * np + 1], pa0, pa1, pa2, pa3, b2, b3);
            }
        }

        __syncthreads();
    }

    // ---- epilogue ----
    const float inv0 = 1.0f / l0;
    const float inv1 = 1.0f / l1;
    #pragma unroll
    for (int nt = 0; nt < 16; nt++) {
        const int col = h * HD_ + nt * 8 + 2 * tq;
        *(__half2*)&aout[(long)(b * S_ + row0) * D_ + col] =
            __floats2half2_rn(o[nt][0] * inv0, o[nt][1] * inv0);
        *(__half2*)&aout[(long)(b * S_ + row1) * D_ + col] =
            __floats2half2_rn(o[nt][2] * inv1, o[nt][3] * inv1);
    }
}

// ===========================================================================
extern "C" void kernel_launch(void* const* d_in, const int* in_sizes, int n_in,
                              void* d_out, int out_size)
{
    const float* x      = (const float*)d_in[0];
    const float* amask  = (const float*)d_in[1];
    const float* W_attn = (const float*)d_in[2];
    const float* b_attn = (const float*)d_in[3];
    const float* W_proj = (const float*)d_in[4];
    const float* b_proj = (const float*)d_in[5];
    float* out = (float*)d_out;

    __half *xh, *wah, *wph, *qkv, *attn;
    cudaGetSymbolAddress((void**)&xh,   g_xh);
    cudaGetSymbolAddress((void**)&wah,  g_wah);
    cudaGetSymbolAddress((void**)&wph,  g_wph);
    cudaGetSymbolAddress((void**)&qkv,  g_qkv);
    cudaGetSymbolAddress((void**)&attn, g_attn);

    cudaFuncSetAttribute(gemm_mma_f16<true>,
                         cudaFuncAttributeMaxDynamicSharedMemorySize, GEMM_SMEM);
    cudaFuncSetAttribute(gemm_mma_f16<false>,
                         cudaFuncAttributeMaxDynamicSharedMemorySize, GEMM_SMEM);
    cudaFuncSetAttribute(attn_mma_f16,
                         cudaFuncAttributeMaxDynamicSharedMemorySize, ATTN_SMEM);

    const int M = B_ * S_;   // 8192

    // 0) fused fp32 -> fp16 prepass
    f2h_all<<<(N4_TOTAL + 255) / 256, 256>>>(x, W_attn, W_proj, xh, wah, wph);

    // 1) QKV GEMM (fp16 mma) -> fp16
    {
        dim3 grid((3 * D_) / 128, M / 128);
        gemm_mma_f16<true><<<grid, 256, GEMM_SMEM>>>(xh, wah, b_attn, qkv, 3 * D_);
    }

    // 2) Tensor-core flash attention (fp16, 64-query CTAs, 2 CTAs/SM)
    {
        dim3 grid(S_ / QROWS, B_ * H_);
        attn_mma_f16<<<grid, 128, ATTN_SMEM>>>(qkv, amask, attn);
    }

    // 3) Output projection (fp16 mma) -> fp32
    {
        dim3 grid(D_ / 128, M / 128);
        gemm_mma_f16<false><<<grid, 256, GEMM_SMEM>>>(attn, wph, b_proj, out, D_);
    }
}

// round 13
// speedup vs baseline: 1.0765x; 1.0137x over previous
#include <cuda_runtime.h>
#include <cuda_fp16.h>
#include <math.h>
#include <stdint.h>

// Problem constants
#define B_   8
#define S_   1024
#define D_   1024
#define H_   8
#define HD_  128
#define PREFIX_LEN 77
#define MASKED_BIAS -10000.0f
#define LOG2E 1.4426950408889634f

// Scratch (no cudaMalloc allowed)
__device__ __half g_xh[B_ * S_ * D_];
__device__ __half g_wah[D_ * 3 * D_];
__device__ __half g_wph[D_ * D_];
__device__ __half g_qkv[B_ * S_ * 3 * D_];
__device__ __half g_attn[B_ * S_ * D_];

// ===========================================================================
// helpers
// ===========================================================================
__device__ __forceinline__ uint32_t s2u(const void* p) {
    return (uint32_t)__cvta_generic_to_shared((void*)p);
}
#define CP_ASYNC16(dst_u32, src_ptr) \
    asm volatile("cp.async.cg.shared.global [%0], [%1], 16;" \
                 :: "r"(dst_u32), "l"(src_ptr))
#define CP_COMMIT() asm volatile("cp.async.commit_group;" ::: "memory")
#define CP_WAIT0()  asm volatile("cp.async.wait_group 0;"  ::: "memory")
#define CP_WAIT1()  asm volatile("cp.async.wait_group 1;"  ::: "memory")

#define LDSM_X4(r0, r1, r2, r3, addr) \
    asm volatile("ldmatrix.sync.aligned.m8n8.x4.shared.b16 {%0,%1,%2,%3}, [%4];" \
        : "=r"(r0), "=r"(r1), "=r"(r2), "=r"(r3) : "r"(addr))
#define LDSM_X4_T(r0, r1, r2, r3, addr) \
    asm volatile("ldmatrix.sync.aligned.m8n8.x4.trans.shared.b16 {%0,%1,%2,%3}, [%4];" \
        : "=r"(r0), "=r"(r1), "=r"(r2), "=r"(r3) : "r"(addr))

#define MMA_F16(d, a0, a1, a2, a3, b0, b1) \
    asm volatile( \
        "mma.sync.aligned.m16n8k16.row.col.f32.f16.f16.f32 " \
        "{%0,%1,%2,%3}, {%4,%5,%6,%7}, {%8,%9}, {%0,%1,%2,%3};" \
        : "+f"((d)[0]), "+f"((d)[1]), "+f"((d)[2]), "+f"((d)[3]) \
        : "r"(a0), "r"(a1), "r"(a2), "r"(a3), "r"(b0), "r"(b1))

__device__ __forceinline__ uint32_t h2u(__half2 v) {
    return *(uint32_t*)&v;
}
__device__ __forceinline__ float ex2f(float x) {
    float r;
    asm("ex2.approx.ftz.f32 %0, %1;" : "=f"(r) : "f"(x));
    return r;
}

// ===========================================================================
// fused fp32 -> fp16 conversion prepass
// ===========================================================================
#define N4_X  (B_ * S_ * D_ / 4)
#define N4_WA (3 * D_ * D_ / 4)
#define N4_WP (D_ * D_ / 4)
#define N4_TOTAL (N4_X + N4_WA + N4_WP)

__global__ __launch_bounds__(256) void f2h_all(
    const float* __restrict__ x, const float* __restrict__ wa,
    const float* __restrict__ wp,
    __half* __restrict__ xh, __half* __restrict__ wah, __half* __restrict__ wph)
{
    int i = blockIdx.x * blockDim.x + threadIdx.x;
    if (i >= N4_TOTAL) return;
    const float* src;
    __half* dst;
    int j;
    if (i < N4_X)              { src = x;  dst = xh;  j = i; }
    else if (i < N4_X + N4_WA) { src = wa; dst = wah; j = i - N4_X; }
    else                       { src = wp; dst = wph; j = i - N4_X - N4_WA; }
    float4 v = ((const float4*)src)[j];
    __half2* d2 = (__half2*)dst;
    d2[2 * j]     = __floats2half2_rn(v.x, v.y);
    d2[2 * j + 1] = __floats2half2_rn(v.z, v.w);
}

// ===========================================================================
// FP16 mma GEMM (unchanged — proven at legacy-HMMA ceiling)
// ===========================================================================
#define KKg 1024
#define BKg 64
#define NCHg (KKg / BKg)
#define SA_H 72
#define SB_H 136
#define A_BYTES (128 * SA_H * 2)
#define B_BYTES (BKg * SB_H * 2)
#define STAGE_BYTES (A_BYTES + B_BYTES)
#define GEMM_SMEM (3 * STAGE_BYTES)

template <bool OUT_HALF>
__global__ __launch_bounds__(256, 2) void gemm_mma_f16(
    const __half* __restrict__ A, const __half* __restrict__ Bw,
    const float* __restrict__ bias, void* __restrict__ Cv, int N)
{
    extern __shared__ char smraw[];
    const uint32_t su = s2u(smraw);

    const int t    = threadIdx.x;
    const int wid  = t >> 5;
    const int lane = t & 31;
    const int g    = lane >> 2;
    const int tq   = lane & 3;
    const int wm   = wid >> 2;
    const int wn   = wid & 3;
    const int m0   = blockIdx.y * 128;
    const int n0   = blockIdx.x * 128;

    const int l15  = lane & 15;
    const int l7   = lane & 7;
    const int hi8a = (lane & 16) ? 8 : 0;
    const int hi8b = (lane & 8)  ? 8 : 0;

    auto load_chunk = [&](int ch, int stg) {
        const int k0 = ch * BKg;
        const uint32_t base = su + (uint32_t)stg * STAGE_BYTES;
        #pragma unroll
        for (int i = 0; i < 4; i++) {
            int idx = t + i * 256;
            int r = idx >> 3, c = idx & 7;
            uint32_t dst = base + (uint32_t)(r * (SA_H * 2) + c * 16);
            const __half* src = A + (long)(m0 + r) * KKg + k0 + c * 8;
            CP_ASYNC16(dst, src);
        }
        #pragma unroll
        for (int i = 0; i < 4; i++) {
            int idx = t + i * 256;
            int r = idx >> 4, c = idx & 15;
            uint32_t dst = base + A_BYTES + (uint32_t)(r * (SB_H * 2) + c * 16);
            const __half* src = Bw + (long)(k0 + r) * N + n0 + c * 8;
            CP_ASYNC16(dst, src);
        }
    };

    load_chunk(0, 0); CP_COMMIT();
    load_chunk(1, 1); CP_COMMIT();

    float acc[4][4][4];
    #pragma unroll
    for (int mt = 0; mt < 4; mt++)
        #pragma unroll
        for (int nt = 0; nt < 4; nt++)
            #pragma unroll
            for (int r = 0; r < 4; r++) acc[mt][nt][r] = 0.0f;

    int stage = 0;
    for (int i = 0; i < NCHg; i++) {
        if (i + 2 < NCHg) CP_WAIT1(); else CP_WAIT0();
        __syncthreads();

        if (i + 2 < NCHg) {
            int nstg = stage + 2; if (nstg >= 3) nstg -= 3;
            load_chunk(i + 2, nstg);
        }
        CP_COMMIT();

        const uint32_t sa = su + (uint32_t)stage * STAGE_BYTES;
        const uint32_t sb = sa + A_BYTES;

        #pragma unroll
        for (int ks = 0; ks < 4; ks++) {
            uint32_t af[4][4], bf[4][2];
            #pragma unroll
            for (int mt = 0; mt < 4; mt++) {
                uint32_t addr = sa + 2u * (uint32_t)(
                    (wm * 64 + mt * 16 + l15) * SA_H + ks * 16 + hi8a);
                LDSM_X4(af[mt][0], af[mt][1], af[mt][2], af[mt][3], addr);
            }
            #pragma unroll
            for (int np = 0; np < 2; np++) {
                uint32_t addr = sb + 2u * (uint32_t)(
                    (ks * 16 + l7 + hi8b) * SB_H + wn * 32 + np * 16 + hi8a);
                LDSM_X4_T(bf[2 * np][0], bf[2 * np][1],
                          bf[2 * np + 1][0], bf[2 * np + 1][1], addr);
            }
            #pragma unroll
            for (int mt = 0; mt < 4; mt++)
                #pragma unroll
                for (int nt = 0; nt < 4; nt++)
                    MMA_F16(acc[mt][nt], af[mt][0], af[mt][1], af[mt][2],
                            af[mt][3], bf[nt][0], bf[nt][1]);
        }
        if (++stage == 3) stage = 0;
    }

    #pragma unroll
    for (int nt = 0; nt < 4; nt++) {
        const int col = n0 + wn * 32 + nt * 8 + tq * 2;
        const float bx = bias[col];
        const float by = bias[col + 1];
        #pragma unroll
        for (int mt = 0; mt < 4; mt++) {
            const int row = m0 + wm * 64 + mt * 16 + g;
            if (OUT_HALF) {
                __half* C = (__half*)Cv;
                *(__half2*)&C[(long)row * N + col] =
                    __floats2half2_rn(acc[mt][nt][0] + bx, acc[mt][nt][1] + by);
                *(__half2*)&C[(long)(row + 8) * N + col] =
                    __floats2half2_rn(acc[mt][nt][2] + bx, acc[mt][nt][3] + by);
            } else {
                float* C = (float*)Cv;
                *(float2*)&C[(long)row * N + col] =
                    make_float2(acc[mt][nt][0] + bx, acc[mt][nt][1] + by);
                *(float2*)&C[(long)(row + 8) * N + col] =
                    make_float2(acc[mt][nt][2] + bx, acc[mt][nt][3] + by);
            }
        }
    }
}

// ===========================================================================
// FP16 flash attention: 64-query CTAs, 128 threads, 2 CTAs/SM.
// log2-domain softmax (ex2.approx, amask pre-scaled in SMEM) + interior-tile
// fast path.
// ===========================================================================
#define AST 136
#define QROWS 64
#define KV_STAGE (64 * AST * 2)            // K+V per stage (halves)
#define KV_OFF (QROWS * AST)               // 8704 halves
#define AM_OFF (KV_OFF + 2 * KV_STAGE)     // halves offset of amask region
#define ATTN_SMEM (AM_OFF * 2 + S_ * 4)    // 87040 + 4096 = 91136 bytes

__global__ __launch_bounds__(128, 2) void attn_mma_f16(
    const __half* __restrict__ qkv,     // [B,S,3D] fp16
    const float* __restrict__ amask,    // [B,1,1,S] fp32
    __half* __restrict__ aout)          // [B,S,D] fp16
{
    extern __shared__ __half smh[];
    const uint32_t su = s2u(smh);
    const uint32_t Qu = su;
    float* amS = (float*)(smh + AM_OFF);

    const int t    = threadIdx.x;      // 0..127
    const int wid  = t >> 5;           // 0..3
    const int lane = t & 31;
    const int g    = lane >> 2;
    const int tq   = lane & 3;
    const int qt   = gridDim.x - 1 - blockIdx.x;   // largest-work first
    const int q0   = qt * QROWS;
    const int bh   = blockIdx.y;
    const int b    = bh >> 3;
    const int h    = bh & 7;
    const int rb   = wid * 16;

    const int l15  = lane & 15;
    const int l7   = lane & 7;
    const int hi8a = (lane & 16) ? 8 : 0;
    const int hi8b = (lane & 8)  ? 8 : 0;

    const float qs2   = rsqrtf((float)HD_) * LOG2E;   // qscale * log2(e)
    const float BIAS2 = MASKED_BIAS * LOG2E;
    int nkt = qt + 1;
    if (nkt < 2) nkt = 2;

    // ---- issue Q tile load ----
    #pragma unroll
    for (int i = 0; i < 8; i++) {
        int idx = t + i * 128;
        int row = idx >> 4;
        int c   = idx & 15;
        uint32_t dst = su + 2u * (uint32_t)(row * AST + c * 8);
        CP_ASYNC16(dst, &qkv[(long)(b * S_ + q0 + row) * (3 * D_) + h * HD_ + c * 8]);
    }
    CP_COMMIT();

    // ---- preload amask*log2e into SMEM (one-time) ----
    #pragma unroll
    for (int i = 0; i < 8; i++) {
        int idx = t + i * 128;
        amS[idx] = amask[b * S_ + idx] * LOG2E;
    }

    auto load_kv = [&](int kt, int stg) {
        const uint32_t kbase = su + 2u * (uint32_t)(KV_OFF + stg * KV_STAGE);
        #pragma unroll
        for (int i = 0; i < 16; i++) {
            int idx = t + i * 128;          // 0..2047; first 1024 K, rest V
            int row = (idx & 1023) >> 4;
            int c   = idx & 15;
            long src = (long)(b * S_ + kt * 64 + row) * (3 * D_) + h * HD_ + c * 8;
            if (idx < 1024) {
                CP_ASYNC16(kbase + 2u * (uint32_t)(row * AST + c * 8),
                           &qkv[src + D_]);
            } else {
                CP_ASYNC16(kbase + 2u * (uint32_t)((64 + row) * AST + c * 8),
                           &qkv[src + 2 * D_]);
            }
        }
        CP_COMMIT();
    };

    load_kv(0, 0);

    CP_WAIT1();               // Q resident (KV0 in flight); also orders amS
    __syncthreads();
    uint32_t qf[8][4];
    #pragma unroll
    for (int ks = 0; ks < 8; ks++) {
        LDSM_X4(qf[ks][0], qf[ks][1], qf[ks][2], qf[ks][3],
                Qu + 2u * (uint32_t)((rb + l15) * AST + ks * 16 + hi8a));
    }

    float o[16][4];
    #pragma unroll
    for (int nt = 0; nt < 16; nt++)
        #pragma unroll
        for (int r = 0; r < 4; r++) o[nt][r] = 0.0f;
    float m0 = -1e30f, m1 = -1e30f, l0 = 0.0f, l1 = 0.0f;

    const int row0 = q0 + rb + g;
    const int row1 = row0 + 8;

    for (int kt = 0; kt < nkt; kt++) {
        if (kt + 1 < nkt) { load_kv(kt + 1, (kt + 1) & 1); CP_WAIT1(); }
        else              { CP_WAIT0(); }
        __syncthreads();

        const uint32_t Ku = su + 2u * (uint32_t)(KV_OFF + (kt & 1) * KV_STAGE);
        const uint32_t Vu = Ku + 2u * (uint32_t)(64 * AST);

        // ---- S = Q @ K^T : warp tile 16x64 ----
        float sacc[8][4];
        #pragma unroll
        for (int nt = 0; nt < 8; nt++)
            #pragma unroll
            for (int r = 0; r < 4; r++) sacc[nt][r] = 0.0f;

        #pragma unroll
        for (int ks = 0; ks < 8; ks++) {
            #pragma unroll
            for (int np = 0; np < 4; np++) {
                uint32_t b0, b1, b2, b3;
                LDSM_X4(b0, b1, b2, b3,
                        Ku + 2u * (uint32_t)((np * 16 + l7 + hi8a) * AST + ks * 16 + hi8b));
                MMA_F16(sacc[2 * np],     qf[ks][0], qf[ks][1], qf[ks][2], qf[ks][3], b0, b1);
                MMA_F16(sacc[2 * np + 1], qf[ks][0], qf[ks][1], qf[ks][2], qf[ks][3], b2, b3);
            }
        }

        // ---- scale + mask + online softmax (log2 domain) ----
        float mloc0 = -1e30f, mloc1 = -1e30f;
        if (kt < qt) {
            // Interior tile: provably fully unmasked.
            #pragma unroll
            for (int nt = 0; nt < 8; nt++) {
                const int c0 = kt * 64 + nt * 8 + 2 * tq;
                float2 am = *(const float2*)&amS[c0];
                sacc[nt][0] = sacc[nt][0] * qs2 + am.x;
                sacc[nt][1] = sacc[nt][1] * qs2 + am.y;
                sacc[nt][2] = sacc[nt][2] * qs2 + am.x;
                sacc[nt][3] = sacc[nt][3] * qs2 + am.y;
                mloc0 = fmaxf(mloc0, fmaxf(sacc[nt][0], sacc[nt][1]));
                mloc1 = fmaxf(mloc1, fmaxf(sacc[nt][2], sacc[nt][3]));
            }
        } else {
            #pragma unroll
            for (int nt = 0; nt < 8; nt++) {
                const int c0 = kt * 64 + nt * 8 + 2 * tq;
                const int c1 = c0 + 1;
                float2 am = *(const float2*)&amS[c0];
                bool ok00 = (row0 < PREFIX_LEN) ? (c0 < PREFIX_LEN) : (c0 <= row0);
                bool ok01 = (row0 < PREFIX_LEN) ? (c1 < PREFIX_LEN) : (c1 <= row0);
                bool ok10 = (row1 < PREFIX_LEN) ? (c0 < PREFIX_LEN) : (c0 <= row1);
                bool ok11 = (row1 < PREFIX_LEN) ? (c1 < PREFIX_LEN) : (c1 <= row1);
                sacc[nt][0] = (ok00 ? sacc[nt][0] * qs2 : BIAS2) + am.x;
                sacc[nt][1] = (ok01 ? sacc[nt][1] * qs2 : BIAS2) + am.y;
                sacc[nt][2] = (ok10 ? sacc[nt][2] * qs2 : BIAS2) + am.x;
                sacc[nt][3] = (ok11 ? sacc[nt][3] * qs2 : BIAS2) + am.y;
                mloc0 = fmaxf(mloc0, fmaxf(sacc[nt][0], sacc[nt][1]));
                mloc1 = fmaxf(mloc1, fmaxf(sacc[nt][2], sacc[nt][3]));
            }
        }
        mloc0 = fmaxf(mloc0, __shfl_xor_sync(0xFFFFFFFF, mloc0, 1));
        mloc0 = fmaxf(mloc0, __shfl_xor_sync(0xFFFFFFFF, mloc0, 2));
        mloc1 = fmaxf(mloc1, __shfl_xor_sync(0xFFFFFFFF, mloc1, 1));
        mloc1 = fmaxf(mloc1, __shfl_xor_sync(0xFFFFFFFF, mloc1, 2));

        const float mn0 = fmaxf(m0, mloc0);
        const float mn1 = fmaxf(m1, mloc1);
        const float sc0 = ex2f(m0 - mn0);
        const float sc1 = ex2f(m1 - mn1);
        m0 = mn0; m1 = mn1;

        float ls0 = 0.0f, ls1 = 0.0f;
        #pragma unroll
        for (int nt = 0; nt < 8; nt++) {
            sacc[nt][0] = ex2f(sacc[nt][0] - mn0);
            sacc[nt][1] = ex2f(sacc[nt][1] - mn0);
            sacc[nt][2] = ex2f(sacc[nt][2] - mn1);
            sacc[nt][3] = ex2f(sacc[nt][3] - mn1);
            ls0 += sacc[nt][0] + sacc[nt][1];
            ls1 += sacc[nt][2] + sacc[nt][3];
        }
        ls0 += __shfl_xor_sync(0xFFFFFFFF, ls0, 1);
        ls0 += __shfl_xor_sync(0xFFFFFFFF, ls0, 2);
        ls1 += __shfl_xor_sync(0xFFFFFFFF, ls1, 1);
        ls1 += __shfl_xor_sync(0xFFFFFFFF, ls1, 2);
        l0 = l0 * sc0 + ls0;
        l1 = l1 * sc1 + ls1;

        #pragma unroll
        for (int nt = 0; nt < 16; nt++) {
            o[nt][0] *= sc0; o[nt][1] *= sc0;
            o[nt][2] *= sc1; o[nt][3] *= sc1;
        }

        // ---- O += P @ V : P stays in registers ----
        #pragma unroll
        for (int kk = 0; kk < 4; kk++) {
            uint32_t pa0 = h2u(__floats2half2_rn(sacc[2 * kk][0],     sacc[2 * kk][1]));
            uint32_t pa1 = h2u(__floats2half2_rn(sacc[2 * kk][2],     sacc[2 * kk][3]));
            uint32_t pa2 = h2u(__floats2half2_rn(sacc[2 * kk + 1][0], sacc[2 * kk + 1][1]));
            uint32_t pa3 = h2u(__floats2half2_rn(sacc[2 * kk + 1][2], sacc[2 * kk + 1][3]));
            #pragma unroll
            for (int np = 0; np < 8; np++) {
                uint32_t b0, b1, b2, b3;
                LDSM_X4_T(b0, b1, b2, b3,
                          Vu + 2u * (uint32_t)((kk * 16 + l7 + hi8b) * AST + np * 16 + hi8a));
                MMA_F16(o[2 * np],     pa0, pa1, pa2, pa3, b0, b1);
                MMA_F16(o[2 * np + 1], pa0, pa1, pa2, pa3, b2, b3);
            }
        }

        __syncthreads();
    }

    // ---- epilogue ----
    const float inv0 = 1.0f / l0;
    const float inv1 = 1.0f / l1;
    #pragma unroll
    for (int nt = 0; nt < 16; nt++) {
        const int col = h * HD_ + nt * 8 + 2 * tq;
        *(__half2*)&aout[(long)(b * S_ + row0) * D_ + col] =
            __floats2half2_rn(o[nt][0] * inv0, o[nt][1] * inv0);
        *(__half2*)&aout[(long)(b * S_ + row1) * D_ + col] =
            __floats2half2_rn(o[nt][2] * inv1, o[nt][3] * inv1);
    }
}

// ===========================================================================
extern "C" void kernel_launch(void* const* d_in, const int* in_sizes, int n_in,
                              void* d_out, int out_size)
{
    const float* x      = (const float*)d_in[0];
    const float* amask  = (const float*)d_in[1];
    const float* W_attn = (const float*)d_in[2];
    const float* b_attn = (const float*)d_in[3];
    const float* W_proj = (const float*)d_in[4];
    const float* b_proj = (const float*)d_in[5];
    float* out = (float*)d_out;

    __half *xh, *wah, *wph, *qkv, *attn;
    cudaGetSymbolAddress((void**)&xh,   g_xh);
    cudaGetSymbolAddress((void**)&wah,  g_wah);
    cudaGetSymbolAddress((void**)&wph,  g_wph);
    cudaGetSymbolAddress((void**)&qkv,  g_qkv);
    cudaGetSymbolAddress((void**)&attn, g_attn);

    cudaFuncSetAttribute(gemm_mma_f16<true>,
                         cudaFuncAttributeMaxDynamicSharedMemorySize, GEMM_SMEM);
    cudaFuncSetAttribute(gemm_mma_f16<false>,
                         cudaFuncAttributeMaxDynamicSharedMemorySize, GEMM_SMEM);
    cudaFuncSetAttribute(attn_mma_f16,
                         cudaFuncAttributeMaxDynamicSharedMemorySize, ATTN_SMEM);

    const int M = B_ * S_;   // 8192

    // 0) fused fp32 -> fp16 prepass
    f2h_all<<<(N4_TOTAL + 255) / 256, 256>>>(x, W_attn, W_proj, xh, wah, wph);

    // 1) QKV GEMM (fp16 mma) -> fp16
    {
        dim3 grid((3 * D_) / 128, M / 128);
        gemm_mma_f16<true><<<grid, 256, GEMM_SMEM>>>(xh, wah, b_attn, qkv, 3 * D_);
    }

    // 2) Tensor-core flash attention (fp16, 64-query CTAs, 2 CTAs/SM)
    {
        dim3 grid(S_ / QROWS, B_ * H_);
        attn_mma_f16<<<grid, 128, ATTN_SMEM>>>(qkv, amask, attn);
    }

    // 3) Output projection (fp16 mma) -> fp32
    {
        dim3 grid(D_ / 128, M / 128);
        gemm_mma_f16<false><<<grid, 256, GEMM_SMEM>>>(attn, wph, b_proj, out, D_);
    }
}